// round 5
// baseline (speedup 1.0000x reference)
#include <cuda_runtime.h>
#include <cstdint>

typedef unsigned long long ull;

#define B_TILE   16
#define NTHREADS 576
#define T        64
#define D        128
#define CTILE    16
#define NTILES   8            // 128 / 16
#define RSTRIDE  20           // padded weight tile row stride (floats)
#define NROWS    576          // wk(128)+wq(128)+wv(128)+wo(128)+V(64)
#define TILE_F   (NROWS * RSTRIDE)     // 11520 floats per buffer

// dynamic smem layout (float offsets)
#define OFF_WS   0                         // 2 * 11520 = 23040 (also reused as Y buffer)
#define OFF_Y    0                         // [b][row<512] : 16*512 = 8192 floats (reuse)
#define OFF_ST   (2 * TILE_F)              // 23040 : stT 128 cols * 20 = 2560
#define OFF_X    (OFF_ST + 128 * RSTRIDE)  // 25600 : 1024
#define OFF_V    (OFF_X + B_TILE * T)      // 26624 : 1024
#define OFF_S    (OFF_V + B_TILE * T)      // 27648
#define OFF_D    (OFF_S + B_TILE)          // 27664
#define OFF_MN   (OFF_D + B_TILE)          // 27680
#define OFF_MX   (OFF_MN + B_TILE)         // 27696
#define SMEM_F   (OFF_MX + B_TILE)         // 27712 floats = 110848 B

__device__ __forceinline__ ull ffma2(ull a, ull b, ull c) {
    ull r;
    asm("fma.rn.f32x2 %0, %1, %2, %3;" : "=l"(r) : "l"(a), "l"(b), "l"(c));
    return r;
}
__device__ __forceinline__ ull pack2(float v) {
    ull r; asm("mov.b64 %0, {%1, %1};" : "=l"(r) : "f"(v)); return r;
}
__device__ __forceinline__ void unpack2(ull a, float& lo, float& hi) {
    asm("mov.b64 {%0, %1}, %2;" : "=f"(lo), "=f"(hi) : "l"(a));
}
__device__ __forceinline__ float ex2f(float x) {
    float r; asm("ex2.approx.ftz.f32 %0, %1;" : "=f"(r) : "f"(x)); return r;
}
__device__ __forceinline__ void cp16(unsigned int dst, const void* src) {
    asm volatile("cp.async.ca.shared.global [%0], [%1], 16;" :: "r"(dst), "l"(src));
}
__device__ __forceinline__ void cp_commit() {
    asm volatile("cp.async.commit_group;" ::: "memory");
}
template<int N> __device__ __forceinline__ void cp_wait() {
    asm volatile("cp.async.wait_group %0;" :: "n"(N) : "memory");
}

__global__ void __launch_bounds__(NTHREADS, 2)
fused_hyper_attn(const float* __restrict__ x, const float* __restrict__ state,
                 const float* __restrict__ wk_w, const float* __restrict__ wk_b,
                 const float* __restrict__ wq_w, const float* __restrict__ wq_b,
                 const float* __restrict__ wv_w, const float* __restrict__ wv_b,
                 const float* __restrict__ wo_w, const float* __restrict__ wo_b,
                 const float* __restrict__ V_w,  const float* __restrict__ V_b,
                 float* __restrict__ out)
{
    extern __shared__ __align__(16) float sm[];
    const int t  = threadIdx.x;
    const int b0 = blockIdx.x * B_TILE;
    const unsigned int sm_u32 = (unsigned int)__cvta_generic_to_shared(sm);

    // ---- stage weight tiles (cp.async, double buffered); row source picked by row ----
    #define STAGE(TI)                                                          \
    do {                                                                       \
        const int c0_ = (TI) * CTILE;                                          \
        const unsigned int wb_ = sm_u32 + (OFF_WS + ((TI) & 1) * TILE_F) * 4;  \
        _Pragma("unroll")                                                      \
        for (int i_ = 0; i_ < 4; i_++) {                                       \
            int q_ = t + i_ * NTHREADS;        /* 0..2303 */                   \
            int row_ = q_ >> 2, cq_ = q_ & 3;                                  \
            const float* src_;                                                 \
            if      (row_ < 128) src_ = wk_w + (size_t)row_ * D;               \
            else if (row_ < 256) src_ = wq_w + (size_t)(row_ - 128) * D;       \
            else if (row_ < 384) src_ = wv_w + (size_t)(row_ - 256) * D;       \
            else if (row_ < 512) src_ = wo_w + (size_t)(row_ - 384) * D;       \
            else                 src_ = V_w  + (size_t)(row_ - 512) * D;       \
            cp16(wb_ + (unsigned int)(row_ * RSTRIDE + cq_ * 4) * 4,           \
                 src_ + c0_ + cq_ * 4);                                        \
        }                                                                      \
        cp_commit();                                                           \
    } while (0)

    STAGE(0);
    STAGE(1);

    // ---- stage x (16x64) and transposed state stT[col][b] (stride 20) ----
    if (t < 256)
        ((float4*)(sm + OFF_X))[t] = ((const float4*)(x + (size_t)b0 * T))[t];
    if (t < 512) {
        const int b  = t >> 5;         // batch
        const int c4 = t & 31;         // float4 column group
        float4 sv = ((const float4*)(state + (size_t)b0 * D))[b * 32 + c4];
        sm[OFF_ST + (c4 * 4 + 0) * RSTRIDE + b] = sv.x;
        sm[OFF_ST + (c4 * 4 + 1) * RSTRIDE + b] = sv.y;
        sm[OFF_ST + (c4 * 4 + 2) * RSTRIDE + b] = sv.z;
        sm[OFF_ST + (c4 * 4 + 3) * RSTRIDE + b] = sv.w;
    }
    __syncthreads();   // x + stT visible

    // ---- per-batch min/max of x (16 threads, overlapped with tile waits) ----
    if (t < B_TILE) {
        const float* xr = sm + OFF_X + t * T;
        float mn = xr[0], mx = mn;
        #pragma unroll
        for (int k = 1; k < T; k++) {
            float v = xr[k];
            mn = fminf(mn, v); mx = fmaxf(mx, v);
        }
        sm[OFF_MN + t] = mn; sm[OFF_MX + t] = mx;
    }

    // ---- main loop: thread owns weight row `t`; 16 batches packed in 8 f32x2 accs
    ull acc[8];
    #pragma unroll
    for (int k = 0; k < 8; k++) acc[k] = 0ull;

    for (int ti = 0; ti < NTILES; ti++) {
        if (ti < NTILES - 1) cp_wait<1>(); else cp_wait<0>();
        __syncthreads();

        const float4* wt4 = (const float4*)(sm + OFF_WS + (ti & 1) * TILE_F);
        #pragma unroll
        for (int cg = 0; cg < 4; cg++) {
            float4 w4 = wt4[t * 5 + cg];
            #pragma unroll
            for (int c = 0; c < 4; c++) {
                float wc = (c == 0) ? w4.x : (c == 1) ? w4.y : (c == 2) ? w4.z : w4.w;
                const int col = ti * CTILE + cg * 4 + c;
                const ulonglong2* sp = (const ulonglong2*)(sm + OFF_ST + col * RSTRIDE);
                ull wd = pack2(wc);
                ulonglong2 s0 = sp[0], s1 = sp[1], s2 = sp[2], s3 = sp[3];
                acc[0] = ffma2(s0.x, wd, acc[0]);
                acc[1] = ffma2(s0.y, wd, acc[1]);
                acc[2] = ffma2(s1.x, wd, acc[2]);
                acc[3] = ffma2(s1.y, wd, acc[3]);
                acc[4] = ffma2(s2.x, wd, acc[4]);
                acc[5] = ffma2(s2.y, wd, acc[5]);
                acc[6] = ffma2(s3.x, wd, acc[6]);
                acc[7] = ffma2(s3.y, wd, acc[7]);
            }
        }

        __syncthreads();
        if (ti + 2 < NTILES) STAGE(ti + 2);
    }

    // ---- finalize: |y| to exchange buffer (mats), v to sm_v (V rows) ----
    {
        float bias;
        if (t < 128)      bias = wk_b[t];
        else if (t < 256) bias = wq_b[t - 128];
        else if (t < 384) bias = wv_b[t - 256];
        else if (t < 512) bias = wo_b[t - 384];
        else              bias = V_b[t - 512];

        if (t < 512) {
            #pragma unroll
            for (int k = 0; k < 8; k++) {
                float lo, hi; unpack2(acc[k], lo, hi);
                sm[OFF_Y + (2 * k + 0) * 512 + t] = fabsf(lo + bias);
                sm[OFF_Y + (2 * k + 1) * 512 + t] = fabsf(hi + bias);
            }
        } else {
            const int rV = t - 512;
            #pragma unroll
            for (int k = 0; k < 8; k++) {
                float lo, hi; unpack2(acc[k], lo, hi);
                sm[OFF_V + (2 * k + 0) * T + rV] = lo + bias;
                sm[OFF_V + (2 * k + 1) * T + rV] = hi + bias;
            }
        }
    }
    __syncthreads();

    // ---- s[b] / d[b]: per-warp tasks, product + reduce over e (no atomics) ----
    {
        const int warp = t >> 5, lane = t & 31;
        for (int task = warp; task < 32; task += 18) {
            const int pr = task >> 4, bb = task & 15;
            const float* ya = sm + OFF_Y + bb * 512 + pr * 256;
            float p = 0.f;
            #pragma unroll
            for (int k = 0; k < 4; k++) {
                int e = lane + k * 32;
                p += ya[e] * ya[128 + e];
            }
            #pragma unroll
            for (int off = 16; off > 0; off >>= 1)
                p += __shfl_xor_sync(0xffffffffu, p, off);
            if (lane == 0) sm[(pr ? OFF_D : OFF_S) + bb] = p;
        }
    }
    __syncthreads();

    // ---- epilogue: per (b,q) softmax over k of c*x_q*x_k (log2 domain), then elu
    if (t < 512) {
        const float inv = 0.08838834764831843f * 1.4426950408889634f;  // log2e/sqrt(128)
        #pragma unroll
        for (int i = 0; i < 2; i++) {
            const int idx = t + i * 512;
            const int b = idx >> 6, q = idx & 63;
            const float* xr = sm + OFF_X + b * T;
            const float4* xr4 = (const float4*)xr;
            float a2 = xr[q] * (sm[OFF_S + b] * inv);
            float m2 = fmaxf(a2 * sm[OFF_MX + b], a2 * sm[OFF_MN + b]);
            float sum = 0.f, ws = 0.f;
            #pragma unroll 4
            for (int j = 0; j < 16; j++) {
                float4 xv = xr4[j];
                float e0 = ex2f(fmaf(a2, xv.x, -m2)); sum += e0; ws = fmaf(e0, xv.x, ws);
                float e1 = ex2f(fmaf(a2, xv.y, -m2)); sum += e1; ws = fmaf(e1, xv.y, ws);
                float e2 = ex2f(fmaf(a2, xv.z, -m2)); sum += e2; ws = fmaf(e2, xv.z, ws);
                float e3 = ex2f(fmaf(a2, xv.w, -m2)); sum += e3; ws = fmaf(e3, xv.w, ws);
            }
            float m = __fdividef(ws, sum);
            float r = fmaf(m, sm[OFF_D + b], sm[OFF_V + b * T + q]);
            out[(size_t)(b0 + b) * T + q] = r > 0.f ? r : expm1f(r);
        }
    }
}

extern "C" void kernel_launch(void* const* d_in, const int* in_sizes, int n_in,
                              void* d_out, int out_size) {
    const float* x     = (const float*)d_in[0];
    const float* state = (const float*)d_in[1];
    const float* wk_w  = (const float*)d_in[2];
    const float* wk_b  = (const float*)d_in[3];
    const float* wq_w  = (const float*)d_in[4];
    const float* wq_b  = (const float*)d_in[5];
    const float* wv_w  = (const float*)d_in[6];
    const float* wv_b  = (const float*)d_in[7];
    const float* wo_w  = (const float*)d_in[8];
    const float* wo_b  = (const float*)d_in[9];
    const float* V_w   = (const float*)d_in[10];
    const float* V_b   = (const float*)d_in[11];

    static int configured = 0;
    if (!configured) {
        cudaFuncSetAttribute(fused_hyper_attn,
                             cudaFuncAttributeMaxDynamicSharedMemorySize,
                             SMEM_F * 4);
        configured = 1;
    }

    int nb   = in_sizes[0] / T;        // 4096 batches
    int grid = nb / B_TILE;            // 256 blocks
    fused_hyper_attn<<<grid, NTHREADS, SMEM_F * 4>>>(x, state,
                                                     wk_w, wk_b, wq_w, wq_b,
                                                     wv_w, wv_b, wo_w, wo_b,
                                                     V_w, V_b, (float*)d_out);
}